// round 11
// baseline (speedup 1.0000x reference)
#include <cuda_runtime.h>
#include <mma.h>
#include <cstdint>
#include <cstddef>

using namespace nvcuda;

constexpr int Tn  = 2048;
constexpr int Bn  = 2;
constexpr int En  = 1024;
constexpr int Hn  = 16;
constexpr int Mn  = Tn * Bn;

__device__ float g_q[(size_t)Mn * En];
__device__ float g_k[(size_t)Mn * En];
__device__ float g_v[(size_t)Mn * En];
__device__ float g_attn[(size_t)Mn * En];

__device__ __forceinline__ float hi_part(float v) {
    return __uint_as_float(__float_as_uint(v) & 0xffffe000u);
}
__device__ __forceinline__ float rn_tf32(float v) {
    uint32_t r;
    asm("cvt.rna.tf32.f32 %0, %1;" : "=r"(r) : "f"(v));
    return __uint_as_float(r);
}
__device__ __forceinline__ void split4(float4 v, float4& hi, float4& lo) {
    hi.x = hi_part(v.x); lo.x = v.x - hi.x;
    hi.y = hi_part(v.y); lo.y = v.y - hi.y;
    hi.z = hi_part(v.z); lo.z = v.z - hi.z;
    hi.w = hi_part(v.w); lo.w = v.w - hi.w;
}
__device__ __forceinline__ void cp_async16(uint32_t s_addr, const void* gptr) {
    asm volatile("cp.async.ca.shared.global [%0], [%1], 16;" :: "r"(s_addr), "l"(gptr));
}
__device__ __forceinline__ void cp_async_commit() {
    asm volatile("cp.async.commit_group;" ::: "memory");
}
__device__ __forceinline__ void cp_async_wait_all0() {
    asm volatile("cp.async.wait_group 0;" ::: "memory");
}

// ---------------------------------------------------------------------------
// GEMM: C = (A @ W^T + bias) * alpha, optional tf32-RN rounding of output.
// 3xTF32 (both operands split). Register-staged global prefetch: next k-tile
// LDGs issued before the MMA phase so LDG latency hides under MMA.
// ---------------------------------------------------------------------------
__global__ __launch_bounds__(256, 2) void gemm_xwt_kernel(
    const float* __restrict__ A, const float* __restrict__ W,
    const float* __restrict__ bias, float* __restrict__ C, float alpha, int rnout)
{
    extern __shared__ float sm[];
    float* s_ahi = sm;             // 128 x 36
    float* s_alo = sm + 4608;
    float* s_bhi = sm + 9216;      // 64 x 36
    float* s_blo = sm + 11520;

    const int tid = threadIdx.x;
    const int wid = tid >> 5;
    const int wi  = wid & 3;
    const int wj  = wid >> 2;
    const int m0  = blockIdx.y * 128;
    const int n0  = blockIdx.x * 64;

    wmma::fragment<wmma::accumulator, 16, 16, 8, float> acc[2][2];
    #pragma unroll
    for (int i = 0; i < 2; i++)
        #pragma unroll
        for (int j = 0; j < 2; j++)
            wmma::fill_fragment(acc[i][j], 0.0f);

    const float* Ab = A + (size_t)m0 * En;
    const float* Wb = W + (size_t)n0 * En;

    const int ra_r[4] = { (tid) >> 3, (tid + 256) >> 3, (tid + 512) >> 3, (tid + 768) >> 3 };
    const int ra_c = (tid & 7) * 4;
    const int rw_r[2] = { (tid) >> 3, (tid + 256) >> 3 };

    float4 ra[4], rw[2];
    #pragma unroll
    for (int u = 0; u < 4; u++) ra[u] = *(const float4*)(Ab + (size_t)ra_r[u] * En + ra_c);
    #pragma unroll
    for (int u = 0; u < 2; u++) rw[u] = *(const float4*)(Wb + (size_t)rw_r[u] * En + ra_c);

    for (int k0 = 0; k0 < En; k0 += 32) {
        // split + store staged regs
        #pragma unroll
        for (int u = 0; u < 4; u++) {
            float4 hi, lo; split4(ra[u], hi, lo);
            *(float4*)(s_ahi + ra_r[u] * 36 + ra_c) = hi;
            *(float4*)(s_alo + ra_r[u] * 36 + ra_c) = lo;
        }
        #pragma unroll
        for (int u = 0; u < 2; u++) {
            float4 hi, lo; split4(rw[u], hi, lo);
            *(float4*)(s_bhi + rw_r[u] * 36 + ra_c) = hi;
            *(float4*)(s_blo + rw_r[u] * 36 + ra_c) = lo;
        }
        __syncthreads();

        if (k0 + 32 < En) {
            #pragma unroll
            for (int u = 0; u < 4; u++) ra[u] = *(const float4*)(Ab + (size_t)ra_r[u] * En + k0 + 32 + ra_c);
            #pragma unroll
            for (int u = 0; u < 2; u++) rw[u] = *(const float4*)(Wb + (size_t)rw_r[u] * En + k0 + 32 + ra_c);
        }

        #pragma unroll
        for (int kk = 0; kk < 4; kk++) {
            wmma::fragment<wmma::matrix_a, 16, 16, 8, wmma::precision::tf32, wmma::row_major> ahi[2], alo[2];
            wmma::fragment<wmma::matrix_b, 16, 16, 8, wmma::precision::tf32, wmma::col_major> bhi[2], blo[2];
            #pragma unroll
            for (int i = 0; i < 2; i++) {
                wmma::load_matrix_sync(ahi[i], s_ahi + (wi * 32 + i * 16) * 36 + kk * 8, 36);
                wmma::load_matrix_sync(alo[i], s_alo + (wi * 32 + i * 16) * 36 + kk * 8, 36);
            }
            #pragma unroll
            for (int j = 0; j < 2; j++) {
                wmma::load_matrix_sync(bhi[j], s_bhi + (wj * 32 + j * 16) * 36 + kk * 8, 36);
                wmma::load_matrix_sync(blo[j], s_blo + (wj * 32 + j * 16) * 36 + kk * 8, 36);
            }
            #pragma unroll
            for (int i = 0; i < 2; i++)
                #pragma unroll
                for (int j = 0; j < 2; j++) {
                    wmma::mma_sync(acc[i][j], ahi[i], bhi[j], acc[i][j]);
                    wmma::mma_sync(acc[i][j], ahi[i], blo[j], acc[i][j]);
                    wmma::mma_sync(acc[i][j], alo[i], bhi[j], acc[i][j]);
                }
        }
        __syncthreads();
    }

    float* csm = sm;
    #pragma unroll
    for (int i = 0; i < 2; i++)
        #pragma unroll
        for (int j = 0; j < 2; j++)
            wmma::store_matrix_sync(csm + (wi * 32 + i * 16) * 68 + (wj * 32 + j * 16),
                                    acc[i][j], 68, wmma::mem_row_major);
    __syncthreads();
    for (int i = tid; i < 2048; i += 256) {
        int r = i >> 4, c4 = i & 15;
        float4 v = *(float4*)(csm + r * 68 + c4 * 4);
        int n = n0 + c4 * 4;
        v.x = (v.x + bias[n + 0]) * alpha;
        v.y = (v.y + bias[n + 1]) * alpha;
        v.z = (v.z + bias[n + 2]) * alpha;
        v.w = (v.w + bias[n + 3]) * alpha;
        if (rnout) {
            v.x = rn_tf32(v.x); v.y = rn_tf32(v.y);
            v.z = rn_tf32(v.z); v.w = rn_tf32(v.w);
        }
        *(float4*)(C + (size_t)(m0 + r) * En + n) = v;
    }
}

// ---------------------------------------------------------------------------
// Attention. Q/K/V arrive pre-rounded to tf32-RN -> loads are pure cp.async.
//   S  = Q_rn @ K_rn^T          (1 MMA per pair)
//   O += (P_hi + P_lo) @ V_rn   (P split exact: truncation bias is the killer)
// Pipeline: K(i+1) streams into kt during exp+PV(i) (kt dead after S-MMA);
// V double-buffered; bias tile prefetched into regs under S-MMA; lsum via
// per-thread register partials.  6 tiles = 111.9KB -> 2 CTA/SM.
// ---------------------------------------------------------------------------
__global__ __launch_bounds__(256, 2) void attn_kernel(
    const float* __restrict__ q, const float* __restrict__ k, const float* __restrict__ v,
    const float* __restrict__ bias, const int* __restrict__ mask,
    float* __restrict__ out)
{
    extern __shared__ float sm[];
    float* qt    = sm;               // 64 x 72
    float* kt    = sm + 4608;
    float* vt0   = sm + 2 * 4608;
    float* vt1   = sm + 3 * 4608;
    float* sp    = sm + 4 * 4608;    // S -> P_hi -> O
    float* plo   = sm + 5 * 4608;    // P_lo
    float* lpart = sm + 6 * 4608;    // 64 x 4 partial row sums
    int*   smk   = (int*)(sm + 6 * 4608 + 256);  // 64 mask values

    const int tid = threadIdx.x;
    const int wid = tid >> 5;
    const int wi  = wid >> 1;
    const int wj0 = (wid & 1) * 2;
    const int t0  = blockIdx.x * 64;
    const int bh  = blockIdx.y;
    const int b   = bh / Hn;
    const int h   = bh % Hn;

    uint32_t smem_base = (uint32_t)__cvta_generic_to_shared(sm);
    const size_t qkv_off = (size_t)b * En + (size_t)h * 64;

    // prologue: Q, K(0), V(0) via cp.async
    for (int i = tid; i < 1024; i += 256) {
        int r = i >> 4, c4 = (i & 15) * 4;
        uint32_t d = (r * 72 + c4) * 4;
        cp_async16(smem_base + d,                    q + (size_t)(t0 + r) * Bn * En + qkv_off + c4);
        cp_async16(smem_base + 4608 * 4 + d,         k + (size_t)r * Bn * En + qkv_off + c4);
        cp_async16(smem_base + 2 * 4608 * 4 + d,     v + (size_t)r * Bn * En + qkv_off + c4);
    }
    cp_async_commit();

    wmma::fragment<wmma::accumulator, 16, 16, 8, float> oacc[2];
    wmma::fill_fragment(oacc[0], 0.0f);
    wmma::fill_fragment(oacc[1], 0.0f);

    const float* biasBH = bias + (size_t)bh * Tn * Tn;
    const int* maskB = mask + b * Tn;

    const int te = tid >> 2;          // exp-loop row 0..63
    const int qe = (tid & 3) * 16;    // exp-loop col base
    float lacc = 0.0f;

    for (int s0 = 0, it = 0; s0 < Tn; s0 += 64, it++) {
        float* vcur = (it & 1) ? vt1 : vt0;
        uint32_t vnxt_off = ((it & 1) ? 2 : 3) * 4608 * 4;

        cp_async_wait_all0();
        __syncthreads();          // K(i),V(i) ready; prev readers of all bufs done

        // bias prefetch (latency hides under S-MMA) + mask tile
        float4 br[4];
        const float* bp = biasBH + (size_t)(t0 + te) * Tn + s0 + qe;
        br[0] = *(const float4*)(bp + 0);
        br[1] = *(const float4*)(bp + 4);
        br[2] = *(const float4*)(bp + 8);
        br[3] = *(const float4*)(bp + 12);
        if (tid < 64) smk[tid] = maskB[s0 + tid];

        // S = Q_rn @ K_rn^T (single MMA per pair)
        {
            wmma::fragment<wmma::accumulator, 16, 16, 8, float> sacc[2];
            wmma::fill_fragment(sacc[0], 0.0f);
            wmma::fill_fragment(sacc[1], 0.0f);
            #pragma unroll
            for (int kk = 0; kk < 8; kk++) {
                wmma::fragment<wmma::matrix_a, 16, 16, 8, wmma::precision::tf32, wmma::row_major> ah;
                wmma::load_matrix_sync(ah, qt + (wi * 16) * 72 + kk * 8, 72);
                #pragma unroll
                for (int j = 0; j < 2; j++) {
                    wmma::fragment<wmma::matrix_b, 16, 16, 8, wmma::precision::tf32, wmma::col_major> bk_;
                    wmma::load_matrix_sync(bk_, kt + ((wj0 + j) * 16) * 72 + kk * 8, 72);
                    wmma::mma_sync(sacc[j], ah, bk_, sacc[j]);
                }
            }
            wmma::store_matrix_sync(sp + (wi * 16) * 72 + wj0 * 16,       sacc[0], 72, wmma::mem_row_major);
            wmma::store_matrix_sync(sp + (wi * 16) * 72 + (wj0 + 1) * 16, sacc[1], 72, wmma::mem_row_major);
        }
        __syncthreads();          // S visible; kt now dead

        // stream K(i+1) into kt (overlaps exp + PV)
        if (s0 + 64 < Tn) {
            for (int i = tid; i < 1024; i += 256) {
                int r = i >> 4, c4 = (i & 15) * 4;
                cp_async16(smem_base + 4608 * 4 + (r * 72 + c4) * 4,
                           k + (size_t)(s0 + 64 + r) * Bn * En + qkv_off + c4);
            }
        }

        // exp: thread handles row te, 16 contiguous cols at qe
        {
            const int4* mrow = (const int4*)(smk + qe);
            float* sprow = sp  + te * 72 + qe;
            float* plrow = plo + te * 72 + qe;
            #pragma unroll
            for (int jj = 0; jj < 4; jj++) {
                int4 m4 = mrow[jj];
                float4 s4 = *(float4*)(sprow + jj * 4);
                float4 bb = br[jj];
                if (m4.x) s4.x = -1e-16f;
                if (m4.y) s4.y = -1e-16f;
                if (m4.z) s4.z = -1e-16f;
                if (m4.w) s4.w = -1e-16f;
                float px = __expf(s4.x + bb.x);
                float py = __expf(s4.y + bb.y);
                float pz = __expf(s4.z + bb.z);
                float pw = __expf(s4.w + bb.w);
                float4 hi, lo;
                hi.x = hi_part(px); lo.x = px - hi.x;
                hi.y = hi_part(py); lo.y = py - hi.y;
                hi.z = hi_part(pz); lo.z = pz - hi.z;
                hi.w = hi_part(pw); lo.w = pw - hi.w;
                *(float4*)(sprow + jj * 4) = hi;
                *(float4*)(plrow + jj * 4) = lo;
                lacc += px + py + pz + pw;
            }
        }

        // stream V(i+1) into the other V buffer
        if (s0 + 64 < Tn) {
            for (int i = tid; i < 1024; i += 256) {
                int r = i >> 4, c4 = (i & 15) * 4;
                cp_async16(smem_base + vnxt_off + (r * 72 + c4) * 4,
                           v + (size_t)(s0 + 64 + r) * Bn * En + qkv_off + c4);
            }
        }
        cp_async_commit();
        __syncthreads();          // P visible

        // O += (P_hi + P_lo) @ V_rn
        #pragma unroll
        for (int kk = 0; kk < 8; kk++) {
            wmma::fragment<wmma::matrix_a, 16, 16, 8, wmma::precision::tf32, wmma::row_major> ph, pl;
            wmma::load_matrix_sync(ph, sp  + (wi * 16) * 72 + kk * 8, 72);
            wmma::load_matrix_sync(pl, plo + (wi * 16) * 72 + kk * 8, 72);
            #pragma unroll
            for (int j = 0; j < 2; j++) {
                wmma::fragment<wmma::matrix_b, 16, 16, 8, wmma::precision::tf32, wmma::row_major> vv_;
                wmma::load_matrix_sync(vv_, vcur + (kk * 8) * 72 + (wj0 + j) * 16, 72);
                wmma::mma_sync(oacc[j], ph, vv_, oacc[j]);
                wmma::mma_sync(oacc[j], pl, vv_, oacc[j]);
            }
        }
    }

    lpart[te * 4 + (tid & 3)] = lacc;
    __syncthreads();
    wmma::store_matrix_sync(sp + (wi * 16) * 72 + wj0 * 16,       oacc[0], 72, wmma::mem_row_major);
    wmma::store_matrix_sync(sp + (wi * 16) * 72 + (wj0 + 1) * 16, oacc[1], 72, wmma::mem_row_major);
    __syncthreads();
    for (int i = tid; i < 1024; i += 256) {
        int t = i >> 4, c4 = (i & 15) * 4;
        float ls = lpart[t * 4] + lpart[t * 4 + 1] + lpart[t * 4 + 2] + lpart[t * 4 + 3];
        float inv = 1.0f / ls;
        float4 o = *(float4*)(sp + t * 72 + c4);
        o.x *= inv; o.y *= inv; o.z *= inv; o.w *= inv;
        *(float4*)(out + (size_t)(t0 + t) * Bn * En + (size_t)b * En + h * 64 + c4) = o;
    }
}

// ---------------------------------------------------------------------------
extern "C" void kernel_launch(void* const* d_in, const int* in_sizes, int n_in,
                              void* d_out, int out_size)
{
    (void)in_sizes; (void)n_in; (void)out_size;
    const float* x  = (const float*)d_in[0];
    const int* mask = (const int*)d_in[1];
    const float* bias = (const float*)d_in[2];
    const float* Wq = (const float*)d_in[3];
    const float* bq = (const float*)d_in[4];
    const float* Wk = (const float*)d_in[5];
    const float* bk = (const float*)d_in[6];
    const float* Wv = (const float*)d_in[7];
    const float* bv = (const float*)d_in[8];
    const float* Wo = (const float*)d_in[9];
    const float* bo = (const float*)d_in[10];
    float* out = (float*)d_out;

    void *pq, *pk, *pv, *pa;
    cudaGetSymbolAddress(&pq, g_q);
    cudaGetSymbolAddress(&pk, g_k);
    cudaGetSymbolAddress(&pv, g_v);
    cudaGetSymbolAddress(&pa, g_attn);

    const int GEMM_SMEM = 13824 * 4;                        // 55296 B
    const int ATTN_SMEM = (6 * 4608 + 256 + 64) * 4;        // 111872 B -> 2 CTA/SM
    cudaFuncSetAttribute(gemm_xwt_kernel, cudaFuncAttributeMaxDynamicSharedMemorySize, GEMM_SMEM);
    cudaFuncSetAttribute(attn_kernel, cudaFuncAttributeMaxDynamicSharedMemorySize, ATTN_SMEM);

    dim3 ggrid(En / 64, Mn / 128);
    gemm_xwt_kernel<<<ggrid, 256, GEMM_SMEM>>>(x, Wq, bq, (float*)pq, 0.125f, 1);
    gemm_xwt_kernel<<<ggrid, 256, GEMM_SMEM>>>(x, Wk, bk, (float*)pk, 1.0f, 1);
    gemm_xwt_kernel<<<ggrid, 256, GEMM_SMEM>>>(x, Wv, bv, (float*)pv, 1.0f, 1);

    dim3 agrid(Tn / 64, Bn * Hn);
    attn_kernel<<<agrid, 256, ATTN_SMEM>>>((const float*)pq, (const float*)pk,
                                           (const float*)pv, bias, mask, (float*)pa);

    gemm_xwt_kernel<<<ggrid, 256, GEMM_SMEM>>>((const float*)pa, Wo, bo, out, 1.0f, 0);
}

// round 13
// speedup vs baseline: 1.7412x; 1.7412x over previous
#include <cuda_runtime.h>
#include <mma.h>
#include <cstdint>
#include <cstddef>

using namespace nvcuda;

constexpr int Tn  = 2048;
constexpr int Bn  = 2;
constexpr int En  = 1024;
constexpr int Hn  = 16;
constexpr int Mn  = Tn * Bn;

__device__ float g_q[(size_t)Mn * En];
__device__ float g_k[(size_t)Mn * En];
__device__ float g_v[(size_t)Mn * En];
__device__ float g_attn[(size_t)Mn * En];

__device__ __forceinline__ float hi_part(float v) {
    return __uint_as_float(__float_as_uint(v) & 0xffffe000u);
}
__device__ __forceinline__ float rn_tf32(float v) {
    uint32_t r;
    asm("cvt.rna.tf32.f32 %0, %1;" : "=r"(r) : "f"(v));
    return __uint_as_float(r);
}
__device__ __forceinline__ void split4(float4 v, float4& hi, float4& lo) {
    hi.x = hi_part(v.x); lo.x = v.x - hi.x;
    hi.y = hi_part(v.y); lo.y = v.y - hi.y;
    hi.z = hi_part(v.z); lo.z = v.z - hi.z;
    hi.w = hi_part(v.w); lo.w = v.w - hi.w;
}
__device__ __forceinline__ void cp_async16(uint32_t s_addr, const void* gptr) {
    asm volatile("cp.async.ca.shared.global [%0], [%1], 16;" :: "r"(s_addr), "l"(gptr));
}
__device__ __forceinline__ void cp_async_commit() {
    asm volatile("cp.async.commit_group;" ::: "memory");
}
__device__ __forceinline__ void cp_async_wait_all0() {
    asm volatile("cp.async.wait_group 0;" ::: "memory");
}

// ---------------------------------------------------------------------------
// GEMM: C = (A @ W^T + bias) * alpha, optional tf32-RN rounding of output.
// Split-left + RN-right: A split hi/lo (exact), W pre-rounded RN tf32.
// 2 MMAs per tile-pair. R10 mainloop structure (no reg staging, no occ cap).
// ---------------------------------------------------------------------------
__global__ __launch_bounds__(256) void gemm_xwt_kernel(
    const float* __restrict__ A, const float* __restrict__ W,
    const float* __restrict__ bias, float* __restrict__ C, float alpha, int rnout)
{
    extern __shared__ float sm[];
    float* s_ahi = sm;             // 128 x 36
    float* s_alo = sm + 4608;      // 128 x 36
    float* s_bw  = sm + 9216;      // 64  x 36  (W, RN tf32)

    const int tid = threadIdx.x;
    const int wid = tid >> 5;
    const int wi  = wid & 3;
    const int wj  = wid >> 2;
    const int m0  = blockIdx.y * 128;
    const int n0  = blockIdx.x * 64;

    wmma::fragment<wmma::accumulator, 16, 16, 8, float> acc[2][2];
    #pragma unroll
    for (int i = 0; i < 2; i++)
        #pragma unroll
        for (int j = 0; j < 2; j++)
            wmma::fill_fragment(acc[i][j], 0.0f);

    const float* Ab = A + (size_t)m0 * En;
    const float* Wb = W + (size_t)n0 * En;

    for (int k0 = 0; k0 < En; k0 += 32) {
        #pragma unroll
        for (int i = tid; i < 1024; i += 256) {
            int r = i >> 3, c = i & 7;
            float4 v = *(const float4*)(Ab + (size_t)r * En + k0 + c * 4);
            float4 hi, lo; split4(v, hi, lo);
            *(float4*)(s_ahi + r * 36 + c * 4) = hi;
            *(float4*)(s_alo + r * 36 + c * 4) = lo;
        }
        #pragma unroll
        for (int i = tid; i < 512; i += 256) {
            int r = i >> 3, c = i & 7;
            float4 v = *(const float4*)(Wb + (size_t)r * En + k0 + c * 4);
            v.x = rn_tf32(v.x); v.y = rn_tf32(v.y);
            v.z = rn_tf32(v.z); v.w = rn_tf32(v.w);
            *(float4*)(s_bw + r * 36 + c * 4) = v;
        }
        __syncthreads();

        #pragma unroll
        for (int kk = 0; kk < 4; kk++) {
            wmma::fragment<wmma::matrix_a, 16, 16, 8, wmma::precision::tf32, wmma::row_major> ahi[2], alo[2];
            wmma::fragment<wmma::matrix_b, 16, 16, 8, wmma::precision::tf32, wmma::col_major> bw[2];
            #pragma unroll
            for (int i = 0; i < 2; i++) {
                wmma::load_matrix_sync(ahi[i], s_ahi + (wi * 32 + i * 16) * 36 + kk * 8, 36);
                wmma::load_matrix_sync(alo[i], s_alo + (wi * 32 + i * 16) * 36 + kk * 8, 36);
            }
            #pragma unroll
            for (int j = 0; j < 2; j++)
                wmma::load_matrix_sync(bw[j], s_bw + (wj * 32 + j * 16) * 36 + kk * 8, 36);
            #pragma unroll
            for (int i = 0; i < 2; i++)
                #pragma unroll
                for (int j = 0; j < 2; j++) {
                    wmma::mma_sync(acc[i][j], ahi[i], bw[j], acc[i][j]);
                    wmma::mma_sync(acc[i][j], alo[i], bw[j], acc[i][j]);
                }
        }
        __syncthreads();
    }

    float* csm = sm;
    #pragma unroll
    for (int i = 0; i < 2; i++)
        #pragma unroll
        for (int j = 0; j < 2; j++)
            wmma::store_matrix_sync(csm + (wi * 32 + i * 16) * 68 + (wj * 32 + j * 16),
                                    acc[i][j], 68, wmma::mem_row_major);
    __syncthreads();
    for (int i = tid; i < 2048; i += 256) {
        int r = i >> 4, c4 = i & 15;
        float4 v = *(float4*)(csm + r * 68 + c4 * 4);
        int n = n0 + c4 * 4;
        v.x = (v.x + bias[n + 0]) * alpha;
        v.y = (v.y + bias[n + 1]) * alpha;
        v.z = (v.z + bias[n + 2]) * alpha;
        v.w = (v.w + bias[n + 3]) * alpha;
        if (rnout) {
            v.x = rn_tf32(v.x); v.y = rn_tf32(v.y);
            v.z = rn_tf32(v.z); v.w = rn_tf32(v.w);
        }
        *(float4*)(C + (size_t)(m0 + r) * En + n) = v;
    }
}

// ---------------------------------------------------------------------------
// Attention, 128-row Q tile. 8 warps; warp w owns rows [16w,16w+16) x all 64
// cols -> 4 independent accumulator chains per warp for S and for PV (2x ILP
// vs the 64-row version). Q/K/V pre-rounded tf32-RN.
//   S  = Q_rn @ K_rn^T            (1 MMA/pair)
//   O += (P_hi + P_lo) @ V_rn     (P split exact)
// K recycled in place (dead after S), V double-buffered, bias reg-prefetch,
// lsum via register partials. smem 163KB -> 1 CTA/SM.
// ---------------------------------------------------------------------------
__global__ __launch_bounds__(256) void attn_kernel(
    const float* __restrict__ q, const float* __restrict__ k, const float* __restrict__ v,
    const float* __restrict__ bias, const int* __restrict__ mask,
    float* __restrict__ out)
{
    extern __shared__ float sm[];
    float* qt    = sm;                      // 128 x 72
    float* kt    = sm + 9216;               // 64 x 72
    float* vt0   = sm + 9216 + 4608;        // 64 x 72
    float* vt1   = sm + 9216 + 2 * 4608;    // 64 x 72
    float* sp    = sm + 9216 + 3 * 4608;    // 128 x 72 : S -> P_hi -> O
    float* plo   = sp + 9216;               // 128 x 72 : P_lo
    float* lpart = plo + 9216;              // 128 x 2 partial row sums
    int*   smk   = (int*)(lpart + 256);     // 64 mask values

    const int tid  = threadIdx.x;
    const int wid  = tid >> 5;
    const int row0 = wid * 16;
    const int t0   = blockIdx.x * 128;
    const int bh   = blockIdx.y;
    const int b    = bh / Hn;
    const int h    = bh % Hn;

    uint32_t smem_base = (uint32_t)__cvta_generic_to_shared(sm);
    const size_t qkv_off = (size_t)b * En + (size_t)h * 64;

    // prologue: Q(128x64), K(0), V(0) via cp.async
    for (int i = tid; i < 2048; i += 256) {
        int r = i >> 4, c4 = (i & 15) * 4;
        cp_async16(smem_base + (r * 72 + c4) * 4,
                   q + (size_t)(t0 + r) * Bn * En + qkv_off + c4);
    }
    for (int i = tid; i < 1024; i += 256) {
        int r = i >> 4, c4 = (i & 15) * 4;
        uint32_t d = (r * 72 + c4) * 4;
        cp_async16(smem_base + 9216 * 4 + d,          k + (size_t)r * Bn * En + qkv_off + c4);
        cp_async16(smem_base + (9216 + 4608) * 4 + d, v + (size_t)r * Bn * En + qkv_off + c4);
    }
    cp_async_commit();

    wmma::fragment<wmma::accumulator, 16, 16, 8, float> oacc[4];
    #pragma unroll
    for (int j = 0; j < 4; j++) wmma::fill_fragment(oacc[j], 0.0f);

    const float* biasBH = bias + (size_t)bh * Tn * Tn;
    const int* maskB = mask + b * Tn;

    const int te = tid >> 1;            // exp row 0..127
    const int qe = (tid & 1) * 32;      // exp col base
    float lacc = 0.0f;

    for (int s0 = 0, it = 0; s0 < Tn; s0 += 64, it++) {
        float* vcur = (it & 1) ? vt1 : vt0;
        uint32_t vnxt_off = ((it & 1) ? (9216 + 4608) : (9216 + 2 * 4608)) * 4;

        cp_async_wait_all0();
        __syncthreads();          // K(i),V(i) ready; prev readers done

        // bias prefetch (hides under S-MMA) + mask tile
        float4 br[8];
        const float* bp = biasBH + (size_t)(t0 + te) * Tn + s0 + qe;
        #pragma unroll
        for (int jj = 0; jj < 8; jj++) br[jj] = *(const float4*)(bp + jj * 4);
        if (tid < 64) smk[tid] = maskB[s0 + tid];

        // S = Q_rn @ K_rn^T : warp computes 16 x 64 strip, 4 indep chains
        {
            wmma::fragment<wmma::accumulator, 16, 16, 8, float> sacc[4];
            #pragma unroll
            for (int j = 0; j < 4; j++) wmma::fill_fragment(sacc[j], 0.0f);
            #pragma unroll
            for (int kk = 0; kk < 8; kk++) {
                wmma::fragment<wmma::matrix_a, 16, 16, 8, wmma::precision::tf32, wmma::row_major> ah;
                wmma::load_matrix_sync(ah, qt + row0 * 72 + kk * 8, 72);
                #pragma unroll
                for (int j = 0; j < 4; j++) {
                    wmma::fragment<wmma::matrix_b, 16, 16, 8, wmma::precision::tf32, wmma::col_major> bk_;
                    wmma::load_matrix_sync(bk_, kt + (j * 16) * 72 + kk * 8, 72);
                    wmma::mma_sync(sacc[j], ah, bk_, sacc[j]);
                }
            }
            #pragma unroll
            for (int j = 0; j < 4; j++)
                wmma::store_matrix_sync(sp + row0 * 72 + j * 16, sacc[j], 72, wmma::mem_row_major);
        }
        __syncthreads();          // S visible; kt dead

        // stream K(i+1) into kt (overlaps exp + PV)
        if (s0 + 64 < Tn) {
            for (int i = tid; i < 1024; i += 256) {
                int r = i >> 4, c4 = (i & 15) * 4;
                cp_async16(smem_base + 9216 * 4 + (r * 72 + c4) * 4,
                           k + (size_t)(s0 + 64 + r) * Bn * En + qkv_off + c4);
            }
        }

        // exp: thread handles row te, 32 contiguous cols at qe
        {
            float* sprow = sp  + te * 72 + qe;
            float* plrow = plo + te * 72 + qe;
            const int4* mrow = (const int4*)(smk + qe);
            #pragma unroll
            for (int jj = 0; jj < 8; jj++) {
                int4 m4 = mrow[jj];
                float4 s4 = *(float4*)(sprow + jj * 4);
                float4 bb = br[jj];
                if (m4.x) s4.x = -1e-16f;
                if (m4.y) s4.y = -1e-16f;
                if (m4.z) s4.z = -1e-16f;
                if (m4.w) s4.w = -1e-16f;
                float px = __expf(s4.x + bb.x);
                float py = __expf(s4.y + bb.y);
                float pz = __expf(s4.z + bb.z);
                float pw = __expf(s4.w + bb.w);
                float4 hi, lo;
                hi.x = hi_part(px); lo.x = px - hi.x;
                hi.y = hi_part(py); lo.y = py - hi.y;
                hi.z = hi_part(pz); lo.z = pz - hi.z;
                hi.w = hi_part(pw); lo.w = pw - hi.w;
                *(float4*)(sprow + jj * 4) = hi;
                *(float4*)(plrow + jj * 4) = lo;
                lacc += px + py + pz + pw;
            }
        }

        // stream V(i+1) into the other V buffer
        if (s0 + 64 < Tn) {
            for (int i = tid; i < 1024; i += 256) {
                int r = i >> 4, c4 = (i & 15) * 4;
                cp_async16(smem_base + vnxt_off + (r * 72 + c4) * 4,
                           v + (size_t)(s0 + 64 + r) * Bn * En + qkv_off + c4);
            }
        }
        cp_async_commit();
        __syncthreads();          // P visible

        // O += (P_hi + P_lo) @ V_rn : 4 indep chains
        #pragma unroll
        for (int kk = 0; kk < 8; kk++) {
            wmma::fragment<wmma::matrix_a, 16, 16, 8, wmma::precision::tf32, wmma::row_major> ph, pl;
            wmma::load_matrix_sync(ph, sp  + row0 * 72 + kk * 8, 72);
            wmma::load_matrix_sync(pl, plo + row0 * 72 + kk * 8, 72);
            #pragma unroll
            for (int j = 0; j < 4; j++) {
                wmma::fragment<wmma::matrix_b, 16, 16, 8, wmma::precision::tf32, wmma::row_major> vv_;
                wmma::load_matrix_sync(vv_, vcur + (kk * 8) * 72 + j * 16, 72);
                wmma::mma_sync(oacc[j], ph, vv_, oacc[j]);
                wmma::mma_sync(oacc[j], pl, vv_, oacc[j]);
            }
        }
    }

    lpart[te * 2 + (tid & 1)] = lacc;
    __syncthreads();              // PV readers of sp done; lpart visible
    #pragma unroll
    for (int j = 0; j < 4; j++)
        wmma::store_matrix_sync(sp + row0 * 72 + j * 16, oacc[j], 72, wmma::mem_row_major);
    __syncthreads();
    for (int i = tid; i < 2048; i += 256) {
        int t = i >> 4, c4 = (i & 15) * 4;
        float inv = 1.0f / (lpart[t * 2] + lpart[t * 2 + 1]);
        float4 o = *(float4*)(sp + t * 72 + c4);
        o.x *= inv; o.y *= inv; o.z *= inv; o.w *= inv;
        *(float4*)(out + (size_t)(t0 + t) * Bn * En + (size_t)b * En + h * 64 + c4) = o;
    }
}

// ---------------------------------------------------------------------------
extern "C" void kernel_launch(void* const* d_in, const int* in_sizes, int n_in,
                              void* d_out, int out_size)
{
    (void)in_sizes; (void)n_in; (void)out_size;
    const float* x  = (const float*)d_in[0];
    const int* mask = (const int*)d_in[1];
    const float* bias = (const float*)d_in[2];
    const float* Wq = (const float*)d_in[3];
    const float* bq = (const float*)d_in[4];
    const float* Wk = (const float*)d_in[5];
    const float* bk = (const float*)d_in[6];
    const float* Wv = (const float*)d_in[7];
    const float* bv = (const float*)d_in[8];
    const float* Wo = (const float*)d_in[9];
    const float* bo = (const float*)d_in[10];
    float* out = (float*)d_out;

    void *pq, *pk, *pv, *pa;
    cudaGetSymbolAddress(&pq, g_q);
    cudaGetSymbolAddress(&pk, g_k);
    cudaGetSymbolAddress(&pv, g_v);
    cudaGetSymbolAddress(&pa, g_attn);

    const int GEMM_SMEM = 11520 * 4;                                   // 46080 B
    const int ATTN_SMEM = (9216 + 3 * 4608 + 2 * 9216 + 256 + 64) * 4; // 167168 B
    cudaFuncSetAttribute(gemm_xwt_kernel, cudaFuncAttributeMaxDynamicSharedMemorySize, GEMM_SMEM);
    cudaFuncSetAttribute(attn_kernel, cudaFuncAttributeMaxDynamicSharedMemorySize, ATTN_SMEM);

    dim3 ggrid(En / 64, Mn / 128);
    gemm_xwt_kernel<<<ggrid, 256, GEMM_SMEM>>>(x, Wq, bq, (float*)pq, 0.125f, 1);
    gemm_xwt_kernel<<<ggrid, 256, GEMM_SMEM>>>(x, Wk, bk, (float*)pk, 1.0f, 1);
    gemm_xwt_kernel<<<ggrid, 256, GEMM_SMEM>>>(x, Wv, bv, (float*)pv, 1.0f, 1);

    dim3 agrid(Tn / 128, Bn * Hn);   // (16, 32)
    attn_kernel<<<agrid, 256, ATTN_SMEM>>>((const float*)pq, (const float*)pk,
                                           (const float*)pv, bias, mask, (float*)pa);

    gemm_xwt_kernel<<<ggrid, 256, GEMM_SMEM>>>((const float*)pa, Wo, bo, out, 1.0f, 0);
}

// round 14
// speedup vs baseline: 1.9159x; 1.1003x over previous
#include <cuda_runtime.h>
#include <mma.h>
#include <cstdint>
#include <cstddef>

using namespace nvcuda;

constexpr int Tn  = 2048;
constexpr int Bn  = 2;
constexpr int En  = 1024;
constexpr int Hn  = 16;
constexpr int Mn  = Tn * Bn;

__device__ float g_q[(size_t)Mn * En];
__device__ float g_k[(size_t)Mn * En];
__device__ float g_v[(size_t)Mn * En];
__device__ float g_attn[(size_t)Mn * En];

__device__ __forceinline__ float hi_part(float v) {
    return __uint_as_float(__float_as_uint(v) & 0xffffe000u);
}
__device__ __forceinline__ float rn_tf32(float v) {
    uint32_t r;
    asm("cvt.rna.tf32.f32 %0, %1;" : "=r"(r) : "f"(v));
    return __uint_as_float(r);
}
__device__ __forceinline__ void split4(float4 v, float4& hi, float4& lo) {
    hi.x = hi_part(v.x); lo.x = v.x - hi.x;
    hi.y = hi_part(v.y); lo.y = v.y - hi.y;
    hi.z = hi_part(v.z); lo.z = v.z - hi.z;
    hi.w = hi_part(v.w); lo.w = v.w - hi.w;
}
__device__ __forceinline__ void cp_async16(uint32_t s_addr, const void* gptr) {
    asm volatile("cp.async.ca.shared.global [%0], [%1], 16;" :: "r"(s_addr), "l"(gptr));
}
__device__ __forceinline__ void cp_async_commit() {
    asm volatile("cp.async.commit_group;" ::: "memory");
}
__device__ __forceinline__ void cp_async_wait_all0() {
    asm volatile("cp.async.wait_group 0;" ::: "memory");
}

// ---------------------------------------------------------------------------
// GEMM body: C = (A @ W^T + bias) * alpha, optional tf32-RN rounding of out.
// Split-left + RN-right: A split hi/lo (exact), W pre-rounded RN tf32.
// 2 MMAs per tile-pair. 128x64 tile, BK=32, 256 threads.
// ---------------------------------------------------------------------------
__device__ __forceinline__ void gemm_body(
    const float* __restrict__ A, const float* __restrict__ W,
    const float* __restrict__ bias, float* __restrict__ C, float alpha, int rnout,
    float* sm)
{
    float* s_ahi = sm;             // 128 x 36
    float* s_alo = sm + 4608;      // 128 x 36
    float* s_bw  = sm + 9216;      // 64  x 36  (W, RN tf32)

    const int tid = threadIdx.x;
    const int wid = tid >> 5;
    const int wi  = wid & 3;
    const int wj  = wid >> 2;
    const int m0  = blockIdx.y * 128;
    const int n0  = blockIdx.x * 64;

    wmma::fragment<wmma::accumulator, 16, 16, 8, float> acc[2][2];
    #pragma unroll
    for (int i = 0; i < 2; i++)
        #pragma unroll
        for (int j = 0; j < 2; j++)
            wmma::fill_fragment(acc[i][j], 0.0f);

    const float* Ab = A + (size_t)m0 * En;
    const float* Wb = W + (size_t)n0 * En;

    for (int k0 = 0; k0 < En; k0 += 32) {
        #pragma unroll
        for (int i = tid; i < 1024; i += 256) {
            int r = i >> 3, c = i & 7;
            float4 v = *(const float4*)(Ab + (size_t)r * En + k0 + c * 4);
            float4 hi, lo; split4(v, hi, lo);
            *(float4*)(s_ahi + r * 36 + c * 4) = hi;
            *(float4*)(s_alo + r * 36 + c * 4) = lo;
        }
        #pragma unroll
        for (int i = tid; i < 512; i += 256) {
            int r = i >> 3, c = i & 7;
            float4 v = *(const float4*)(Wb + (size_t)r * En + k0 + c * 4);
            v.x = rn_tf32(v.x); v.y = rn_tf32(v.y);
            v.z = rn_tf32(v.z); v.w = rn_tf32(v.w);
            *(float4*)(s_bw + r * 36 + c * 4) = v;
        }
        __syncthreads();

        #pragma unroll
        for (int kk = 0; kk < 4; kk++) {
            wmma::fragment<wmma::matrix_a, 16, 16, 8, wmma::precision::tf32, wmma::row_major> ahi[2], alo[2];
            wmma::fragment<wmma::matrix_b, 16, 16, 8, wmma::precision::tf32, wmma::col_major> bw[2];
            #pragma unroll
            for (int i = 0; i < 2; i++) {
                wmma::load_matrix_sync(ahi[i], s_ahi + (wi * 32 + i * 16) * 36 + kk * 8, 36);
                wmma::load_matrix_sync(alo[i], s_alo + (wi * 32 + i * 16) * 36 + kk * 8, 36);
            }
            #pragma unroll
            for (int j = 0; j < 2; j++)
                wmma::load_matrix_sync(bw[j], s_bw + (wj * 32 + j * 16) * 36 + kk * 8, 36);
            #pragma unroll
            for (int i = 0; i < 2; i++)
                #pragma unroll
                for (int j = 0; j < 2; j++) {
                    wmma::mma_sync(acc[i][j], ahi[i], bw[j], acc[i][j]);
                    wmma::mma_sync(acc[i][j], alo[i], bw[j], acc[i][j]);
                }
        }
        __syncthreads();
    }

    float* csm = sm;
    #pragma unroll
    for (int i = 0; i < 2; i++)
        #pragma unroll
        for (int j = 0; j < 2; j++)
            wmma::store_matrix_sync(csm + (wi * 32 + i * 16) * 68 + (wj * 32 + j * 16),
                                    acc[i][j], 68, wmma::mem_row_major);
    __syncthreads();
    for (int i = tid; i < 2048; i += 256) {
        int r = i >> 4, c4 = i & 15;
        float4 v = *(float4*)(csm + r * 68 + c4 * 4);
        int n = n0 + c4 * 4;
        v.x = (v.x + bias[n + 0]) * alpha;
        v.y = (v.y + bias[n + 1]) * alpha;
        v.z = (v.z + bias[n + 2]) * alpha;
        v.w = (v.w + bias[n + 3]) * alpha;
        if (rnout) {
            v.x = rn_tf32(v.x); v.y = rn_tf32(v.y);
            v.z = rn_tf32(v.z); v.w = rn_tf32(v.w);
        }
        *(float4*)(C + (size_t)(m0 + r) * En + n) = v;
    }
}

// Fused QKV projections: blockIdx.z selects {Wq,Wk,Wv}. Better wave packing.
__global__ __launch_bounds__(256) void gemm_qkv_kernel(
    const float* __restrict__ x,
    const float* __restrict__ Wq, const float* __restrict__ bq, float* __restrict__ Cq,
    const float* __restrict__ Wk, const float* __restrict__ bk, float* __restrict__ Ck,
    const float* __restrict__ Wv, const float* __restrict__ bv, float* __restrict__ Cv)
{
    extern __shared__ float sm[];
    const float* W; const float* bb; float* C; float alpha;
    if (blockIdx.z == 0)      { W = Wq; bb = bq; C = Cq; alpha = 0.125f; }
    else if (blockIdx.z == 1) { W = Wk; bb = bk; C = Ck; alpha = 1.0f; }
    else                      { W = Wv; bb = bv; C = Cv; alpha = 1.0f; }
    gemm_body(x, W, bb, C, alpha, 1, sm);
}

__global__ __launch_bounds__(256) void gemm_xwt_kernel(
    const float* __restrict__ A, const float* __restrict__ W,
    const float* __restrict__ bias, float* __restrict__ C, float alpha, int rnout)
{
    extern __shared__ float sm[];
    gemm_body(A, W, bias, C, alpha, rnout, sm);
}

// ---------------------------------------------------------------------------
// Attention: 128 threads / 4 warps, 64-row Q tile; warp owns 16 rows x 64
// cols -> 4 independent accumulator chains (R13 ILP) AND 111.4KB smem ->
// 2 CTAs/SM (R10 phase overlap: one CTA's exp runs under the other's MMAs).
//   S  = Q_rn @ K_rn^T            (1 MMA/pair)
//   O += (P_hi + P_lo) @ V_rn     (P split exact)
// K recycled in place, V double-buffered, bias reg-prefetch, reg lsum.
// ---------------------------------------------------------------------------
__global__ __launch_bounds__(128, 2) void attn_kernel(
    const float* __restrict__ q, const float* __restrict__ k, const float* __restrict__ v,
    const float* __restrict__ bias, const int* __restrict__ mask,
    float* __restrict__ out)
{
    extern __shared__ float sm[];
    float* qt    = sm;                      // 64 x 72
    float* kt    = sm + 4608;               // 64 x 72
    float* vt0   = sm + 2 * 4608;           // 64 x 72
    float* vt1   = sm + 3 * 4608;           // 64 x 72
    float* sp    = sm + 4 * 4608;           // 64 x 72 : S -> P_hi -> O
    float* plo   = sm + 5 * 4608;           // 64 x 72 : P_lo
    float* lpart = sm + 6 * 4608;           // 64 x 2 partial row sums
    int*   smk   = (int*)(lpart + 128);     // 64 mask values

    const int tid  = threadIdx.x;
    const int wid  = tid >> 5;
    const int row0 = wid * 16;
    const int t0   = blockIdx.x * 64;
    const int bh   = blockIdx.y;
    const int b    = bh / Hn;
    const int h    = bh % Hn;

    uint32_t smem_base = (uint32_t)__cvta_generic_to_shared(sm);
    const size_t qkv_off = (size_t)b * En + (size_t)h * 64;

    // prologue: Q(64x64), K(0), V(0) via cp.async
    for (int i = tid; i < 1024; i += 128) {
        int r = i >> 4, c4 = (i & 15) * 4;
        uint32_t d = (r * 72 + c4) * 4;
        cp_async16(smem_base + d,                q + (size_t)(t0 + r) * Bn * En + qkv_off + c4);
        cp_async16(smem_base + 4608 * 4 + d,     k + (size_t)r * Bn * En + qkv_off + c4);
        cp_async16(smem_base + 2 * 4608 * 4 + d, v + (size_t)r * Bn * En + qkv_off + c4);
    }
    cp_async_commit();

    wmma::fragment<wmma::accumulator, 16, 16, 8, float> oacc[4];
    #pragma unroll
    for (int j = 0; j < 4; j++) wmma::fill_fragment(oacc[j], 0.0f);

    const float* biasBH = bias + (size_t)bh * Tn * Tn;
    const int* maskB = mask + b * Tn;

    const int te = tid >> 1;            // exp row 0..63
    const int qe = (tid & 1) * 32;      // exp col base
    float lacc = 0.0f;

    for (int s0 = 0, it = 0; s0 < Tn; s0 += 64, it++) {
        float* vcur = (it & 1) ? vt1 : vt0;
        uint32_t vnxt_off = ((it & 1) ? 2 : 3) * 4608 * 4;

        cp_async_wait_all0();
        __syncthreads();          // K(i),V(i) ready; prev readers done

        // bias prefetch (hides under S-MMA) + mask tile
        float4 br[8];
        const float* bp = biasBH + (size_t)(t0 + te) * Tn + s0 + qe;
        #pragma unroll
        for (int jj = 0; jj < 8; jj++) br[jj] = *(const float4*)(bp + jj * 4);
        if (tid < 64) smk[tid] = maskB[s0 + tid];

        // S = Q_rn @ K_rn^T : warp computes 16 x 64 strip, 4 indep chains
        {
            wmma::fragment<wmma::accumulator, 16, 16, 8, float> sacc[4];
            #pragma unroll
            for (int j = 0; j < 4; j++) wmma::fill_fragment(sacc[j], 0.0f);
            #pragma unroll
            for (int kk = 0; kk < 8; kk++) {
                wmma::fragment<wmma::matrix_a, 16, 16, 8, wmma::precision::tf32, wmma::row_major> ah;
                wmma::load_matrix_sync(ah, qt + row0 * 72 + kk * 8, 72);
                #pragma unroll
                for (int j = 0; j < 4; j++) {
                    wmma::fragment<wmma::matrix_b, 16, 16, 8, wmma::precision::tf32, wmma::col_major> bk_;
                    wmma::load_matrix_sync(bk_, kt + (j * 16) * 72 + kk * 8, 72);
                    wmma::mma_sync(sacc[j], ah, bk_, sacc[j]);
                }
            }
            #pragma unroll
            for (int j = 0; j < 4; j++)
                wmma::store_matrix_sync(sp + row0 * 72 + j * 16, sacc[j], 72, wmma::mem_row_major);
        }
        __syncthreads();          // S visible; kt dead

        // stream K(i+1) into kt (overlaps exp + PV)
        if (s0 + 64 < Tn) {
            for (int i = tid; i < 1024; i += 128) {
                int r = i >> 4, c4 = (i & 15) * 4;
                cp_async16(smem_base + 4608 * 4 + (r * 72 + c4) * 4,
                           k + (size_t)(s0 + 64 + r) * Bn * En + qkv_off + c4);
            }
        }

        // exp: thread handles row te, 32 contiguous cols at qe
        {
            float* sprow = sp  + te * 72 + qe;
            float* plrow = plo + te * 72 + qe;
            const int4* mrow = (const int4*)(smk + qe);
            #pragma unroll
            for (int jj = 0; jj < 8; jj++) {
                int4 m4 = mrow[jj];
                float4 s4 = *(float4*)(sprow + jj * 4);
                float4 bb = br[jj];
                if (m4.x) s4.x = -1e-16f;
                if (m4.y) s4.y = -1e-16f;
                if (m4.z) s4.z = -1e-16f;
                if (m4.w) s4.w = -1e-16f;
                float px = __expf(s4.x + bb.x);
                float py = __expf(s4.y + bb.y);
                float pz = __expf(s4.z + bb.z);
                float pw = __expf(s4.w + bb.w);
                float4 hi, lo;
                hi.x = hi_part(px); lo.x = px - hi.x;
                hi.y = hi_part(py); lo.y = py - hi.y;
                hi.z = hi_part(pz); lo.z = pz - hi.z;
                hi.w = hi_part(pw); lo.w = pw - hi.w;
                *(float4*)(sprow + jj * 4) = hi;
                *(float4*)(plrow + jj * 4) = lo;
                lacc += px + py + pz + pw;
            }
        }

        // stream V(i+1) into the other V buffer
        if (s0 + 64 < Tn) {
            for (int i = tid; i < 1024; i += 128) {
                int r = i >> 4, c4 = (i & 15) * 4;
                cp_async16(smem_base + vnxt_off + (r * 72 + c4) * 4,
                           v + (size_t)(s0 + 64 + r) * Bn * En + qkv_off + c4);
            }
        }
        cp_async_commit();
        __syncthreads();          // P visible

        // O += (P_hi + P_lo) @ V_rn : 4 indep chains
        #pragma unroll
        for (int kk = 0; kk < 8; kk++) {
            wmma::fragment<wmma::matrix_a, 16, 16, 8, wmma::precision::tf32, wmma::row_major> ph, pl;
            wmma::load_matrix_sync(ph, sp  + row0 * 72 + kk * 8, 72);
            wmma::load_matrix_sync(pl, plo + row0 * 72 + kk * 8, 72);
            #pragma unroll
            for (int j = 0; j < 4; j++) {
                wmma::fragment<wmma::matrix_b, 16, 16, 8, wmma::precision::tf32, wmma::row_major> vv_;
                wmma::load_matrix_sync(vv_, vcur + (kk * 8) * 72 + j * 16, 72);
                wmma::mma_sync(oacc[j], ph, vv_, oacc[j]);
                wmma::mma_sync(oacc[j], pl, vv_, oacc[j]);
            }
        }
    }

    lpart[te * 2 + (tid & 1)] = lacc;
    __syncthreads();              // PV readers of sp done; lpart visible
    #pragma unroll
    for (int j = 0; j < 4; j++)
        wmma::store_matrix_sync(sp + row0 * 72 + j * 16, oacc[j], 72, wmma::mem_row_major);
    __syncthreads();
    for (int i = tid; i < 1024; i += 128) {
        int t = i >> 4, c4 = (i & 15) * 4;
        float inv = 1.0f / (lpart[t * 2] + lpart[t * 2 + 1]);
        float4 o = *(float4*)(sp + t * 72 + c4);
        o.x *= inv; o.y *= inv; o.z *= inv; o.w *= inv;
        *(float4*)(out + (size_t)(t0 + t) * Bn * En + (size_t)b * En + h * 64 + c4) = o;
    }
}

// ---------------------------------------------------------------------------
extern "C" void kernel_launch(void* const* d_in, const int* in_sizes, int n_in,
                              void* d_out, int out_size)
{
    (void)in_sizes; (void)n_in; (void)out_size;
    const float* x  = (const float*)d_in[0];
    const int* mask = (const int*)d_in[1];
    const float* bias = (const float*)d_in[2];
    const float* Wq = (const float*)d_in[3];
    const float* bq = (const float*)d_in[4];
    const float* Wk = (const float*)d_in[5];
    const float* bk = (const float*)d_in[6];
    const float* Wv = (const float*)d_in[7];
    const float* bv = (const float*)d_in[8];
    const float* Wo = (const float*)d_in[9];
    const float* bo = (const float*)d_in[10];
    float* out = (float*)d_out;

    void *pq, *pk, *pv, *pa;
    cudaGetSymbolAddress(&pq, g_q);
    cudaGetSymbolAddress(&pk, g_k);
    cudaGetSymbolAddress(&pv, g_v);
    cudaGetSymbolAddress(&pa, g_attn);

    const int GEMM_SMEM = 11520 * 4;                       // 46080 B
    const int ATTN_SMEM = (6 * 4608 + 128 + 64) * 4;       // 111360 B -> 2 CTA/SM
    cudaFuncSetAttribute(gemm_qkv_kernel, cudaFuncAttributeMaxDynamicSharedMemorySize, GEMM_SMEM);
    cudaFuncSetAttribute(gemm_xwt_kernel, cudaFuncAttributeMaxDynamicSharedMemorySize, GEMM_SMEM);
    cudaFuncSetAttribute(attn_kernel, cudaFuncAttributeMaxDynamicSharedMemorySize, ATTN_SMEM);

    dim3 qkvgrid(En / 64, Mn / 128, 3);   // (16, 32, 3)
    gemm_qkv_kernel<<<qkvgrid, 256, GEMM_SMEM>>>(x, Wq, bq, (float*)pq,
                                                 Wk, bk, (float*)pk,
                                                 Wv, bv, (float*)pv);

    dim3 agrid(Tn / 64, Bn * Hn);         // (32, 32)
    attn_kernel<<<agrid, 128, ATTN_SMEM>>>((const float*)pq, (const float*)pk,
                                           (const float*)pv, bias, mask, (float*)pa);

    dim3 ggrid(En / 64, Mn / 128);
    gemm_xwt_kernel<<<ggrid, 256, GEMM_SMEM>>>((const float*)pa, Wo, bo, out, 1.0f, 0);
}

// round 15
// speedup vs baseline: 1.9746x; 1.0306x over previous
#include <cuda_runtime.h>
#include <mma.h>
#include <cstdint>
#include <cstddef>

using namespace nvcuda;

constexpr int Tn  = 2048;
constexpr int Bn  = 2;
constexpr int En  = 1024;
constexpr int Hn  = 16;
constexpr int Mn  = Tn * Bn;

// Scratch (__device__ globals; no allocation allowed)
__device__ float g_q[(size_t)Mn * En];
__device__ float g_k[(size_t)Mn * En];
__device__ float g_v[(size_t)Mn * En];
__device__ float g_attn[(size_t)Mn * En];   // O hi part
__device__ float g_alo[(size_t)Mn * En];    // O lo part
__device__ float g_xhi[(size_t)Mn * En];
__device__ float g_xlo[(size_t)Mn * En];
__device__ float g_wq[(size_t)En * En];
__device__ float g_wk[(size_t)En * En];
__device__ float g_wv[(size_t)En * En];
__device__ float g_wo[(size_t)En * En];

__device__ __forceinline__ float hi_part(float v) {
    return __uint_as_float(__float_as_uint(v) & 0xffffe000u);
}
__device__ __forceinline__ float rn_tf32(float v) {
    uint32_t r;
    asm("cvt.rna.tf32.f32 %0, %1;" : "=r"(r) : "f"(v));
    return __uint_as_float(r);
}
__device__ __forceinline__ void split4(float4 v, float4& hi, float4& lo) {
    hi.x = hi_part(v.x); lo.x = v.x - hi.x;
    hi.y = hi_part(v.y); lo.y = v.y - hi.y;
    hi.z = hi_part(v.z); lo.z = v.z - hi.z;
    hi.w = hi_part(v.w); lo.w = v.w - hi.w;
}
__device__ __forceinline__ void cp_async16(uint32_t s_addr, const void* gptr) {
    asm volatile("cp.async.ca.shared.global [%0], [%1], 16;" :: "r"(s_addr), "l"(gptr));
}
__device__ __forceinline__ void cp_async_commit() {
    asm volatile("cp.async.commit_group;" ::: "memory");
}
template<int N>
__device__ __forceinline__ void cp_async_wait() {
    asm volatile("cp.async.wait_group %0;" :: "n"(N) : "memory");
}

// ---------------------------------------------------------------------------
// Prep: split x into hi/lo (exact), round W matrices to tf32-RN.
// Pure elementwise; hoists all load-path math out of the GEMM mainloop.
// ---------------------------------------------------------------------------
__global__ __launch_bounds__(256) void prep_kernel(
    const float* __restrict__ x,
    const float* __restrict__ Wq, const float* __restrict__ Wk,
    const float* __restrict__ Wv, const float* __restrict__ Wo)
{
    const int stride = gridDim.x * blockDim.x;
    const int gid = blockIdx.x * blockDim.x + threadIdx.x;
    const int nx = Mn * En / 4;
    const int nw = En * En / 4;
    for (int i = gid; i < nx; i += stride) {
        float4 v = ((const float4*)x)[i];
        float4 hi, lo; split4(v, hi, lo);
        ((float4*)g_xhi)[i] = hi;
        ((float4*)g_xlo)[i] = lo;
    }
    for (int i = gid; i < nw; i += stride) {
        float4 a = ((const float4*)Wq)[i];
        float4 b = ((const float4*)Wk)[i];
        float4 c = ((const float4*)Wv)[i];
        float4 d = ((const float4*)Wo)[i];
        a.x = rn_tf32(a.x); a.y = rn_tf32(a.y); a.z = rn_tf32(a.z); a.w = rn_tf32(a.w);
        b.x = rn_tf32(b.x); b.y = rn_tf32(b.y); b.z = rn_tf32(b.z); b.w = rn_tf32(b.w);
        c.x = rn_tf32(c.x); c.y = rn_tf32(c.y); c.z = rn_tf32(c.z); c.w = rn_tf32(c.w);
        d.x = rn_tf32(d.x); d.y = rn_tf32(d.y); d.z = rn_tf32(d.z); d.w = rn_tf32(d.w);
        ((float4*)g_wq)[i] = a;
        ((float4*)g_wk)[i] = b;
        ((float4*)g_wv)[i] = c;
        ((float4*)g_wo)[i] = d;
    }
}

// ---------------------------------------------------------------------------
// GEMM on pre-split/pre-rounded operands: C = (Ahi+Alo) @ Wrn^T + bias, *alpha.
// Two-stage cp.async double buffer; mainloop = cp.async -> wait -> MMA.
// 128x64 tile, BK=32, 256 threads, 92KB smem -> 2 CTAs/SM.
// ---------------------------------------------------------------------------
__device__ __forceinline__ void gemm_ps_body(
    const float* __restrict__ Ahi, const float* __restrict__ Alo,
    const float* __restrict__ Wrn, const float* __restrict__ bias,
    float* __restrict__ C, float alpha, int rnout, float* sm)
{
    const int tid = threadIdx.x;
    const int wid = tid >> 5;
    const int wi  = wid & 3;
    const int wj  = wid >> 2;
    const int m0  = blockIdx.y * 128;
    const int n0  = blockIdx.x * 64;

    uint32_t sb = (uint32_t)__cvta_generic_to_shared(sm);

    // stage layout (floats): [0,4608) ahi | [4608,9216) alo | [9216,11520) w
    const int r8 = tid >> 3, c8 = (tid & 7) * 4;

    auto load_stage = [&](int st, int k0) {
        uint32_t base = sb + (uint32_t)st * 11520 * 4;
        #pragma unroll
        for (int u = 0; u < 4; u++) {
            int r = r8 + u * 32;
            cp_async16(base + (r * 36 + c8) * 4,
                       Ahi + (size_t)(m0 + r) * En + k0 + c8);
            cp_async16(base + (4608 + r * 36 + c8) * 4,
                       Alo + (size_t)(m0 + r) * En + k0 + c8);
        }
        #pragma unroll
        for (int u = 0; u < 2; u++) {
            int r = r8 + u * 32;
            cp_async16(base + (9216 + r * 36 + c8) * 4,
                       Wrn + (size_t)(n0 + r) * En + k0 + c8);
        }
        cp_async_commit();
    };

    wmma::fragment<wmma::accumulator, 16, 16, 8, float> acc[2][2];
    #pragma unroll
    for (int i = 0; i < 2; i++)
        #pragma unroll
        for (int j = 0; j < 2; j++)
            wmma::fill_fragment(acc[i][j], 0.0f);

    load_stage(0, 0);

    for (int k0 = 0, it = 0; k0 < En; k0 += 32, it++) {
        int s = it & 1;
        if (k0 + 32 < En) {
            load_stage(s ^ 1, k0 + 32);
            cp_async_wait<1>();
        } else {
            cp_async_wait<0>();
        }
        __syncthreads();

        float* s_ahi = sm + s * 11520;
        float* s_alo = s_ahi + 4608;
        float* s_bw  = s_ahi + 9216;

        #pragma unroll
        for (int kk = 0; kk < 4; kk++) {
            wmma::fragment<wmma::matrix_a, 16, 16, 8, wmma::precision::tf32, wmma::row_major> ahi[2], alo[2];
            wmma::fragment<wmma::matrix_b, 16, 16, 8, wmma::precision::tf32, wmma::col_major> bw[2];
            #pragma unroll
            for (int i = 0; i < 2; i++) {
                wmma::load_matrix_sync(ahi[i], s_ahi + (wi * 32 + i * 16) * 36 + kk * 8, 36);
                wmma::load_matrix_sync(alo[i], s_alo + (wi * 32 + i * 16) * 36 + kk * 8, 36);
            }
            #pragma unroll
            for (int j = 0; j < 2; j++)
                wmma::load_matrix_sync(bw[j], s_bw + (wj * 32 + j * 16) * 36 + kk * 8, 36);
            #pragma unroll
            for (int i = 0; i < 2; i++)
                #pragma unroll
                for (int j = 0; j < 2; j++) {
                    wmma::mma_sync(acc[i][j], ahi[i], bw[j], acc[i][j]);
                    wmma::mma_sync(acc[i][j], alo[i], bw[j], acc[i][j]);
                }
        }
        __syncthreads();   // all warps done with stage s before it is overwritten
    }

    float* csm = sm;
    #pragma unroll
    for (int i = 0; i < 2; i++)
        #pragma unroll
        for (int j = 0; j < 2; j++)
            wmma::store_matrix_sync(csm + (wi * 32 + i * 16) * 68 + (wj * 32 + j * 16),
                                    acc[i][j], 68, wmma::mem_row_major);
    __syncthreads();
    for (int i = tid; i < 2048; i += 256) {
        int r = i >> 4, c4 = i & 15;
        float4 v = *(float4*)(csm + r * 68 + c4 * 4);
        int n = n0 + c4 * 4;
        v.x = (v.x + bias[n + 0]) * alpha;
        v.y = (v.y + bias[n + 1]) * alpha;
        v.z = (v.z + bias[n + 2]) * alpha;
        v.w = (v.w + bias[n + 3]) * alpha;
        if (rnout) {
            v.x = rn_tf32(v.x); v.y = rn_tf32(v.y);
            v.z = rn_tf32(v.z); v.w = rn_tf32(v.w);
        }
        *(float4*)(C + (size_t)(m0 + r) * En + n) = v;
    }
}

// Fused QKV projections: blockIdx.z selects {Wq,Wk,Wv} (pre-rounded copies).
__global__ __launch_bounds__(256) void gemm_qkv_kernel(
    const float* __restrict__ bq, const float* __restrict__ bk, const float* __restrict__ bv)
{
    extern __shared__ float sm[];
    if (blockIdx.z == 0)      gemm_ps_body(g_xhi, g_xlo, g_wq, bq, g_q, 0.125f, 1, sm);
    else if (blockIdx.z == 1) gemm_ps_body(g_xhi, g_xlo, g_wk, bk, g_k, 1.0f, 1, sm);
    else                      gemm_ps_body(g_xhi, g_xlo, g_wv, bv, g_v, 1.0f, 1, sm);
}

__global__ __launch_bounds__(256) void gemm_out_kernel(
    const float* __restrict__ bo, float* __restrict__ out)
{
    extern __shared__ float sm[];
    gemm_ps_body(g_attn, g_alo, g_wo, bo, out, 1.0f, 0, sm);
}

// ---------------------------------------------------------------------------
// Attention (R14 structure, unchanged numerics): 128 thr / 4 warps, 64-row Q
// tile; warp owns 16x64 -> 4 indep chains; 111.4KB smem -> 2 CTAs/SM.
// Epilogue writes O as exact hi/lo pair for the pre-split Wo GEMM.
// ---------------------------------------------------------------------------
__global__ __launch_bounds__(128, 2) void attn_kernel(
    const float* __restrict__ q, const float* __restrict__ k, const float* __restrict__ v,
    const float* __restrict__ bias, const int* __restrict__ mask,
    float* __restrict__ out_hi, float* __restrict__ out_lo)
{
    extern __shared__ float sm[];
    float* qt    = sm;                      // 64 x 72
    float* kt    = sm + 4608;
    float* vt0   = sm + 2 * 4608;
    float* vt1   = sm + 3 * 4608;
    float* sp    = sm + 4 * 4608;           // S -> P_hi -> O
    float* plo   = sm + 5 * 4608;           // P_lo
    float* lpart = sm + 6 * 4608;           // 64 x 2 partial row sums
    int*   smk   = (int*)(lpart + 128);     // 64 mask values

    const int tid  = threadIdx.x;
    const int wid  = tid >> 5;
    const int row0 = wid * 16;
    const int t0   = blockIdx.x * 64;
    const int bh   = blockIdx.y;
    const int b    = bh / Hn;
    const int h    = bh % Hn;

    uint32_t smem_base = (uint32_t)__cvta_generic_to_shared(sm);
    const size_t qkv_off = (size_t)b * En + (size_t)h * 64;

    for (int i = tid; i < 1024; i += 128) {
        int r = i >> 4, c4 = (i & 15) * 4;
        uint32_t d = (r * 72 + c4) * 4;
        cp_async16(smem_base + d,                q + (size_t)(t0 + r) * Bn * En + qkv_off + c4);
        cp_async16(smem_base + 4608 * 4 + d,     k + (size_t)r * Bn * En + qkv_off + c4);
        cp_async16(smem_base + 2 * 4608 * 4 + d, v + (size_t)r * Bn * En + qkv_off + c4);
    }
    cp_async_commit();

    wmma::fragment<wmma::accumulator, 16, 16, 8, float> oacc[4];
    #pragma unroll
    for (int j = 0; j < 4; j++) wmma::fill_fragment(oacc[j], 0.0f);

    const float* biasBH = bias + (size_t)bh * Tn * Tn;
    const int* maskB = mask + b * Tn;

    const int te = tid >> 1;
    const int qe = (tid & 1) * 32;
    float lacc = 0.0f;

    for (int s0 = 0, it = 0; s0 < Tn; s0 += 64, it++) {
        float* vcur = (it & 1) ? vt1 : vt0;
        uint32_t vnxt_off = ((it & 1) ? 2 : 3) * 4608 * 4;

        cp_async_wait<0>();
        __syncthreads();

        float4 br[8];
        const float* bp = biasBH + (size_t)(t0 + te) * Tn + s0 + qe;
        #pragma unroll
        for (int jj = 0; jj < 8; jj++) br[jj] = *(const float4*)(bp + jj * 4);
        if (tid < 64) smk[tid] = maskB[s0 + tid];

        {
            wmma::fragment<wmma::accumulator, 16, 16, 8, float> sacc[4];
            #pragma unroll
            for (int j = 0; j < 4; j++) wmma::fill_fragment(sacc[j], 0.0f);
            #pragma unroll
            for (int kk = 0; kk < 8; kk++) {
                wmma::fragment<wmma::matrix_a, 16, 16, 8, wmma::precision::tf32, wmma::row_major> ah;
                wmma::load_matrix_sync(ah, qt + row0 * 72 + kk * 8, 72);
                #pragma unroll
                for (int j = 0; j < 4; j++) {
                    wmma::fragment<wmma::matrix_b, 16, 16, 8, wmma::precision::tf32, wmma::col_major> bk_;
                    wmma::load_matrix_sync(bk_, kt + (j * 16) * 72 + kk * 8, 72);
                    wmma::mma_sync(sacc[j], ah, bk_, sacc[j]);
                }
            }
            #pragma unroll
            for (int j = 0; j < 4; j++)
                wmma::store_matrix_sync(sp + row0 * 72 + j * 16, sacc[j], 72, wmma::mem_row_major);
        }
        __syncthreads();

        if (s0 + 64 < Tn) {
            for (int i = tid; i < 1024; i += 128) {
                int r = i >> 4, c4 = (i & 15) * 4;
                cp_async16(smem_base + 4608 * 4 + (r * 72 + c4) * 4,
                           k + (size_t)(s0 + 64 + r) * Bn * En + qkv_off + c4);
            }
        }

        {
            float* sprow = sp  + te * 72 + qe;
            float* plrow = plo + te * 72 + qe;
            const int4* mrow = (const int4*)(smk + qe);
            #pragma unroll
            for (int jj = 0; jj < 8; jj++) {
                int4 m4 = mrow[jj];
                float4 s4 = *(float4*)(sprow + jj * 4);
                float4 bb = br[jj];
                if (m4.x) s4.x = -1e-16f;
                if (m4.y) s4.y = -1e-16f;
                if (m4.z) s4.z = -1e-16f;
                if (m4.w) s4.w = -1e-16f;
                float px = __expf(s4.x + bb.x);
                float py = __expf(s4.y + bb.y);
                float pz = __expf(s4.z + bb.z);
                float pw = __expf(s4.w + bb.w);
                float4 hi, lo;
                hi.x = hi_part(px); lo.x = px - hi.x;
                hi.y = hi_part(py); lo.y = py - hi.y;
                hi.z = hi_part(pz); lo.z = pz - hi.z;
                hi.w = hi_part(pw); lo.w = pw - hi.w;
                *(float4*)(sprow + jj * 4) = hi;
                *(float4*)(plrow + jj * 4) = lo;
                lacc += px + py + pz + pw;
            }
        }

        if (s0 + 64 < Tn) {
            for (int i = tid; i < 1024; i += 128) {
                int r = i >> 4, c4 = (i & 15) * 4;
                cp_async16(smem_base + vnxt_off + (r * 72 + c4) * 4,
                           v + (size_t)(s0 + 64 + r) * Bn * En + qkv_off + c4);
            }
        }
        cp_async_commit();
        __syncthreads();

        #pragma unroll
        for (int kk = 0; kk < 8; kk++) {
            wmma::fragment<wmma::matrix_a, 16, 16, 8, wmma::precision::tf32, wmma::row_major> ph, pl;
            wmma::load_matrix_sync(ph, sp  + row0 * 72 + kk * 8, 72);
            wmma::load_matrix_sync(pl, plo + row0 * 72 + kk * 8, 72);
            #pragma unroll
            for (int j = 0; j < 4; j++) {
                wmma::fragment<wmma::matrix_b, 16, 16, 8, wmma::precision::tf32, wmma::row_major> vv_;
                wmma::load_matrix_sync(vv_, vcur + (kk * 8) * 72 + j * 16, 72);
                wmma::mma_sync(oacc[j], ph, vv_, oacc[j]);
                wmma::mma_sync(oacc[j], pl, vv_, oacc[j]);
            }
        }
    }

    lpart[te * 2 + (tid & 1)] = lacc;
    __syncthreads();
    #pragma unroll
    for (int j = 0; j < 4; j++)
        wmma::store_matrix_sync(sp + row0 * 72 + j * 16, oacc[j], 72, wmma::mem_row_major);
    __syncthreads();
    for (int i = tid; i < 1024; i += 128) {
        int t = i >> 4, c4 = (i & 15) * 4;
        float inv = 1.0f / (lpart[t * 2] + lpart[t * 2 + 1]);
        float4 o = *(float4*)(sp + t * 72 + c4);
        o.x *= inv; o.y *= inv; o.z *= inv; o.w *= inv;
        float4 hi, lo; split4(o, hi, lo);
        size_t idx = (size_t)(t0 + t) * Bn * En + (size_t)b * En + h * 64 + c4;
        *(float4*)(out_hi + idx) = hi;
        *(float4*)(out_lo + idx) = lo;
    }
}

// ---------------------------------------------------------------------------
extern "C" void kernel_launch(void* const* d_in, const int* in_sizes, int n_in,
                              void* d_out, int out_size)
{
    (void)in_sizes; (void)n_in; (void)out_size;
    const float* x  = (const float*)d_in[0];
    const int* mask = (const int*)d_in[1];
    const float* bias = (const float*)d_in[2];
    const float* Wq = (const float*)d_in[3];
    const float* bq = (const float*)d_in[4];
    const float* Wk = (const float*)d_in[5];
    const float* bk = (const float*)d_in[6];
    const float* Wv = (const float*)d_in[7];
    const float* bv = (const float*)d_in[8];
    const float* Wo = (const float*)d_in[9];
    const float* bo = (const float*)d_in[10];
    float* out = (float*)d_out;

    void *pq, *pk, *pv, *pa, *pal;
    cudaGetSymbolAddress(&pq, g_q);
    cudaGetSymbolAddress(&pk, g_k);
    cudaGetSymbolAddress(&pv, g_v);
    cudaGetSymbolAddress(&pa, g_attn);
    cudaGetSymbolAddress(&pal, g_alo);

    const int GEMM_SMEM = 2 * 11520 * 4;                   // 92160 B -> 2 CTA/SM
    const int ATTN_SMEM = (6 * 4608 + 128 + 64) * 4;       // 111360 B -> 2 CTA/SM
    cudaFuncSetAttribute(gemm_qkv_kernel, cudaFuncAttributeMaxDynamicSharedMemorySize, GEMM_SMEM);
    cudaFuncSetAttribute(gemm_out_kernel, cudaFuncAttributeMaxDynamicSharedMemorySize, GEMM_SMEM);
    cudaFuncSetAttribute(attn_kernel, cudaFuncAttributeMaxDynamicSharedMemorySize, ATTN_SMEM);

    prep_kernel<<<1184, 256>>>(x, Wq, Wk, Wv, Wo);

    dim3 qkvgrid(En / 64, Mn / 128, 3);   // (16, 32, 3)
    gemm_qkv_kernel<<<qkvgrid, 256, GEMM_SMEM>>>(bq, bk, bv);

    dim3 agrid(Tn / 64, Bn * Hn);         // (32, 32)
    attn_kernel<<<agrid, 128, ATTN_SMEM>>>((const float*)pq, (const float*)pk,
                                           (const float*)pv, bias, mask,
                                           (float*)pa, (float*)pal);

    dim3 ggrid(En / 64, Mn / 128);
    gemm_out_kernel<<<ggrid, 256, GEMM_SMEM>>>(bo, out);
}

// round 16
// speedup vs baseline: 2.1920x; 1.1101x over previous
#include <cuda_runtime.h>
#include <mma.h>
#include <cstdint>
#include <cstddef>

using namespace nvcuda;

constexpr int Tn  = 2048;
constexpr int Bn  = 2;
constexpr int En  = 1024;
constexpr int Hn  = 16;
constexpr int Mn  = Tn * Bn;

// Scratch (__device__ globals; no allocation allowed)
__device__ float g_q[(size_t)Mn * En];
__device__ float g_k[(size_t)Mn * En];
__device__ float g_v[(size_t)Mn * En];
__device__ float g_attn[(size_t)Mn * En];   // O hi part
__device__ float g_alo[(size_t)Mn * En];    // O lo part
__device__ float g_xhi[(size_t)Mn * En];
__device__ float g_xlo[(size_t)Mn * En];
__device__ float g_wq[(size_t)En * En];
__device__ float g_wk[(size_t)En * En];
__device__ float g_wv[(size_t)En * En];
__device__ float g_wo[(size_t)En * En];

__device__ __forceinline__ float hi_part(float v) {
    return __uint_as_float(__float_as_uint(v) & 0xffffe000u);
}
__device__ __forceinline__ float rn_tf32(float v) {
    uint32_t r;
    asm("cvt.rna.tf32.f32 %0, %1;" : "=r"(r) : "f"(v));
    return __uint_as_float(r);
}
__device__ __forceinline__ void split4(float4 v, float4& hi, float4& lo) {
    hi.x = hi_part(v.x); lo.x = v.x - hi.x;
    hi.y = hi_part(v.y); lo.y = v.y - hi.y;
    hi.z = hi_part(v.z); lo.z = v.z - hi.z;
    hi.w = hi_part(v.w); lo.w = v.w - hi.w;
}
__device__ __forceinline__ void cp_async16(uint32_t s_addr, const void* gptr) {
    asm volatile("cp.async.ca.shared.global [%0], [%1], 16;" :: "r"(s_addr), "l"(gptr));
}
__device__ __forceinline__ void cp_async_commit() {
    asm volatile("cp.async.commit_group;" ::: "memory");
}
template<int N>
__device__ __forceinline__ void cp_async_wait() {
    asm volatile("cp.async.wait_group %0;" :: "n"(N) : "memory");
}

// ---------------------------------------------------------------------------
// Prep: split x into hi/lo (exact), round W matrices to tf32-RN.
// ---------------------------------------------------------------------------
__global__ __launch_bounds__(256) void prep_kernel(
    const float* __restrict__ x,
    const float* __restrict__ Wq, const float* __restrict__ Wk,
    const float* __restrict__ Wv, const float* __restrict__ Wo)
{
    const int stride = gridDim.x * blockDim.x;
    const int gid = blockIdx.x * blockDim.x + threadIdx.x;
    const int nx = Mn * En / 4;
    const int nw = En * En / 4;
    for (int i = gid; i < nx; i += stride) {
        float4 v = ((const float4*)x)[i];
        float4 hi, lo; split4(v, hi, lo);
        ((float4*)g_xhi)[i] = hi;
        ((float4*)g_xlo)[i] = lo;
    }
    for (int i = gid; i < nw; i += stride) {
        float4 a = ((const float4*)Wq)[i];
        float4 b = ((const float4*)Wk)[i];
        float4 c = ((const float4*)Wv)[i];
        float4 d = ((const float4*)Wo)[i];
        a.x = rn_tf32(a.x); a.y = rn_tf32(a.y); a.z = rn_tf32(a.z); a.w = rn_tf32(a.w);
        b.x = rn_tf32(b.x); b.y = rn_tf32(b.y); b.z = rn_tf32(b.z); b.w = rn_tf32(b.w);
        c.x = rn_tf32(c.x); c.y = rn_tf32(c.y); c.z = rn_tf32(c.z); c.w = rn_tf32(c.w);
        d.x = rn_tf32(d.x); d.y = rn_tf32(d.y); d.z = rn_tf32(d.z); d.w = rn_tf32(d.w);
        ((float4*)g_wq)[i] = a;
        ((float4*)g_wk)[i] = b;
        ((float4*)g_wv)[i] = c;
        ((float4*)g_wo)[i] = d;
    }
}

// ---------------------------------------------------------------------------
// GEMM: C = (Ahi+Alo) @ Wrn^T + bias, *alpha. 64x64 tile, 128 threads
// (4 warps, each 32x32), BK=32, two-stage cp.async. 55.3KB smem -> 4 CTAs/SM
// (phase overlap across 4 independent sync domains).
// ---------------------------------------------------------------------------
__device__ __forceinline__ void gemm_ps_body(
    const float* __restrict__ Ahi, const float* __restrict__ Alo,
    const float* __restrict__ Wrn, const float* __restrict__ bias,
    float* __restrict__ C, float alpha, int rnout, float* sm)
{
    const int tid = threadIdx.x;
    const int wid = tid >> 5;
    const int wi  = wid & 1;      // 32-row group
    const int wj  = wid >> 1;     // 32-col group
    const int m0  = blockIdx.y * 64;
    const int n0  = blockIdx.x * 64;

    uint32_t sb = (uint32_t)__cvta_generic_to_shared(sm);

    // stage layout (floats): [0,2304) ahi | [2304,4608) alo | [4608,6912) w
    const int r8 = tid >> 3, c8 = (tid & 7) * 4;

    auto load_stage = [&](int st, int k0) {
        uint32_t base = sb + (uint32_t)st * 6912 * 4;
        #pragma unroll
        for (int u = 0; u < 4; u++) {
            int r = r8 + u * 16;
            cp_async16(base + (r * 36 + c8) * 4,
                       Ahi + (size_t)(m0 + r) * En + k0 + c8);
            cp_async16(base + (2304 + r * 36 + c8) * 4,
                       Alo + (size_t)(m0 + r) * En + k0 + c8);
            cp_async16(base + (4608 + r * 36 + c8) * 4,
                       Wrn + (size_t)(n0 + r) * En + k0 + c8);
        }
        cp_async_commit();
    };

    wmma::fragment<wmma::accumulator, 16, 16, 8, float> acc[2][2];
    #pragma unroll
    for (int i = 0; i < 2; i++)
        #pragma unroll
        for (int j = 0; j < 2; j++)
            wmma::fill_fragment(acc[i][j], 0.0f);

    load_stage(0, 0);

    for (int k0 = 0, it = 0; k0 < En; k0 += 32, it++) {
        int s = it & 1;
        if (k0 + 32 < En) {
            load_stage(s ^ 1, k0 + 32);
            cp_async_wait<1>();
        } else {
            cp_async_wait<0>();
        }
        __syncthreads();

        float* s_ahi = sm + s * 6912;
        float* s_alo = s_ahi + 2304;
        float* s_bw  = s_ahi + 4608;

        #pragma unroll
        for (int kk = 0; kk < 4; kk++) {
            wmma::fragment<wmma::matrix_a, 16, 16, 8, wmma::precision::tf32, wmma::row_major> ahi[2], alo[2];
            wmma::fragment<wmma::matrix_b, 16, 16, 8, wmma::precision::tf32, wmma::col_major> bw[2];
            #pragma unroll
            for (int i = 0; i < 2; i++) {
                wmma::load_matrix_sync(ahi[i], s_ahi + (wi * 32 + i * 16) * 36 + kk * 8, 36);
                wmma::load_matrix_sync(alo[i], s_alo + (wi * 32 + i * 16) * 36 + kk * 8, 36);
            }
            #pragma unroll
            for (int j = 0; j < 2; j++)
                wmma::load_matrix_sync(bw[j], s_bw + (wj * 32 + j * 16) * 36 + kk * 8, 36);
            #pragma unroll
            for (int i = 0; i < 2; i++)
                #pragma unroll
                for (int j = 0; j < 2; j++) {
                    wmma::mma_sync(acc[i][j], ahi[i], bw[j], acc[i][j]);
                    wmma::mma_sync(acc[i][j], alo[i], bw[j], acc[i][j]);
                }
        }
        __syncthreads();
    }

    float* csm = sm;   // 64 x 68 staging
    #pragma unroll
    for (int i = 0; i < 2; i++)
        #pragma unroll
        for (int j = 0; j < 2; j++)
            wmma::store_matrix_sync(csm + (wi * 32 + i * 16) * 68 + (wj * 32 + j * 16),
                                    acc[i][j], 68, wmma::mem_row_major);
    __syncthreads();
    for (int i = tid; i < 1024; i += 128) {
        int r = i >> 4, c4 = i & 15;
        float4 v = *(float4*)(csm + r * 68 + c4 * 4);
        int n = n0 + c4 * 4;
        v.x = (v.x + bias[n + 0]) * alpha;
        v.y = (v.y + bias[n + 1]) * alpha;
        v.z = (v.z + bias[n + 2]) * alpha;
        v.w = (v.w + bias[n + 3]) * alpha;
        if (rnout) {
            v.x = rn_tf32(v.x); v.y = rn_tf32(v.y);
            v.z = rn_tf32(v.z); v.w = rn_tf32(v.w);
        }
        *(float4*)(C + (size_t)(m0 + r) * En + n) = v;
    }
}

__global__ __launch_bounds__(128, 4) void gemm_qkv_kernel(
    const float* __restrict__ bq, const float* __restrict__ bk, const float* __restrict__ bv)
{
    extern __shared__ float sm[];
    if (blockIdx.z == 0)      gemm_ps_body(g_xhi, g_xlo, g_wq, bq, g_q, 0.125f, 1, sm);
    else if (blockIdx.z == 1) gemm_ps_body(g_xhi, g_xlo, g_wk, bk, g_k, 1.0f, 1, sm);
    else                      gemm_ps_body(g_xhi, g_xlo, g_wv, bv, g_v, 1.0f, 1, sm);
}

__global__ __launch_bounds__(128, 4) void gemm_out_kernel(
    const float* __restrict__ bo, float* __restrict__ out)
{
    extern __shared__ float sm[];
    gemm_ps_body(g_attn, g_alo, g_wo, bo, out, 1.0f, 0, sm);
}

// ---------------------------------------------------------------------------
// Attention: 128 thr / 4 warps, 64-row Q tile, 4 smem tiles = 74.5KB ->
// 3 CTAs/SM.  All of Q,K,V,P are tf32-RN (unbiased) -> 1 MMA per pair for
// both S and PV.  lsum accumulated from the SAME rounded p as the numerator
// (consistent weights -> rounding averages out in the weighted mean).
// V single-buffered: V(i) issued at iter top (vt freed by PV(i-1)), awaited
// by wait_group<1> before PV (K(i+1) may remain in flight).
// ---------------------------------------------------------------------------
__global__ __launch_bounds__(128, 3) void attn_kernel(
    const float* __restrict__ q, const float* __restrict__ k, const float* __restrict__ v,
    const float* __restrict__ bias, const int* __restrict__ mask,
    float* __restrict__ out_hi, float* __restrict__ out_lo)
{
    extern __shared__ float sm[];
    float* qt    = sm;                      // 64 x 72
    float* kt    = sm + 4608;               // 64 x 72
    float* vt    = sm + 2 * 4608;           // 64 x 72
    float* sp    = sm + 3 * 4608;           // 64 x 72 : S -> P -> O
    float* lpart = sm + 4 * 4608;           // 64 x 2 partial row sums
    int*   smk   = (int*)(lpart + 128);     // 64 mask values

    const int tid  = threadIdx.x;
    const int wid  = tid >> 5;
    const int row0 = wid * 16;
    const int t0   = blockIdx.x * 64;
    const int bh   = blockIdx.y;
    const int b    = bh / Hn;
    const int h    = bh % Hn;

    uint32_t smem_base = (uint32_t)__cvta_generic_to_shared(sm);
    const size_t qkv_off = (size_t)b * En + (size_t)h * 64;

    // prologue: Q + K(0) as one group, V(0) as a second group
    for (int i = tid; i < 1024; i += 128) {
        int r = i >> 4, c4 = (i & 15) * 4;
        uint32_t d = (r * 72 + c4) * 4;
        cp_async16(smem_base + d,            q + (size_t)(t0 + r) * Bn * En + qkv_off + c4);
        cp_async16(smem_base + 4608 * 4 + d, k + (size_t)r * Bn * En + qkv_off + c4);
    }
    cp_async_commit();
    for (int i = tid; i < 1024; i += 128) {
        int r = i >> 4, c4 = (i & 15) * 4;
        cp_async16(smem_base + 2 * 4608 * 4 + (r * 72 + c4) * 4,
                   v + (size_t)r * Bn * En + qkv_off + c4);
    }
    cp_async_commit();

    wmma::fragment<wmma::accumulator, 16, 16, 8, float> oacc[4];
    #pragma unroll
    for (int j = 0; j < 4; j++) wmma::fill_fragment(oacc[j], 0.0f);

    const float* biasBH = bias + (size_t)bh * Tn * Tn;
    const int* maskB = mask + b * Tn;

    const int te = tid >> 1;            // exp row 0..63
    const int qe = (tid & 1) * 32;      // exp col base
    float lacc = 0.0f;

    for (int s0 = 0; s0 < Tn; s0 += 64) {
        cp_async_wait<0>();
        __syncthreads();          // K(i) (and V(i) if prologue) ready; vt freed by PV(i-1)

        // V(i) for i>0: vt is free now; load overlaps S + exp
        if (s0 > 0) {
            for (int i = tid; i < 1024; i += 128) {
                int r = i >> 4, c4 = (i & 15) * 4;
                cp_async16(smem_base + 2 * 4608 * 4 + (r * 72 + c4) * 4,
                           v + (size_t)(s0 + r) * Bn * En + qkv_off + c4);
            }
            cp_async_commit();
        }

        // bias prefetch (hides under S-MMA) + mask tile
        float4 br[8];
        const float* bp = biasBH + (size_t)(t0 + te) * Tn + s0 + qe;
        #pragma unroll
        for (int jj = 0; jj < 8; jj++) br[jj] = *(const float4*)(bp + jj * 4);
        if (tid < 64) smk[tid] = maskB[s0 + tid];

        // S = Q_rn @ K_rn^T : warp computes 16 x 64 strip, 4 indep chains
        {
            wmma::fragment<wmma::accumulator, 16, 16, 8, float> sacc[4];
            #pragma unroll
            for (int j = 0; j < 4; j++) wmma::fill_fragment(sacc[j], 0.0f);
            #pragma unroll
            for (int kk = 0; kk < 8; kk++) {
                wmma::fragment<wmma::matrix_a, 16, 16, 8, wmma::precision::tf32, wmma::row_major> ah;
                wmma::load_matrix_sync(ah, qt + row0 * 72 + kk * 8, 72);
                #pragma unroll
                for (int j = 0; j < 4; j++) {
                    wmma::fragment<wmma::matrix_b, 16, 16, 8, wmma::precision::tf32, wmma::col_major> bk_;
                    wmma::load_matrix_sync(bk_, kt + (j * 16) * 72 + kk * 8, 72);
                    wmma::mma_sync(sacc[j], ah, bk_, sacc[j]);
                }
            }
            #pragma unroll
            for (int j = 0; j < 4; j++)
                wmma::store_matrix_sync(sp + row0 * 72 + j * 16, sacc[j], 72, wmma::mem_row_major);
        }
        __syncthreads();          // S visible; kt dead

        // stream K(i+1) into kt (overlaps exp + PV)
        if (s0 + 64 < Tn) {
            for (int i = tid; i < 1024; i += 128) {
                int r = i >> 4, c4 = (i & 15) * 4;
                cp_async16(smem_base + 4608 * 4 + (r * 72 + c4) * 4,
                           k + (size_t)(s0 + 64 + r) * Bn * En + qkv_off + c4);
            }
            cp_async_commit();
        }

        // exp: thread handles row te, 32 contiguous cols at qe.
        // P stored as tf32-RN; lsum accumulates the SAME rounded values.
        {
            float* sprow = sp + te * 72 + qe;
            const int4* mrow = (const int4*)(smk + qe);
            #pragma unroll
            for (int jj = 0; jj < 8; jj++) {
                int4 m4 = mrow[jj];
                float4 s4 = *(float4*)(sprow + jj * 4);
                float4 bb = br[jj];
                if (m4.x) s4.x = -1e-16f;
                if (m4.y) s4.y = -1e-16f;
                if (m4.z) s4.z = -1e-16f;
                if (m4.w) s4.w = -1e-16f;
                float px = rn_tf32(__expf(s4.x + bb.x));
                float py = rn_tf32(__expf(s4.y + bb.y));
                float pz = rn_tf32(__expf(s4.z + bb.z));
                float pw = rn_tf32(__expf(s4.w + bb.w));
                s4.x = px; s4.y = py; s4.z = pz; s4.w = pw;
                *(float4*)(sprow + jj * 4) = s4;
                lacc += px + py + pz + pw;
            }
        }

        cp_async_wait<1>();       // V(i) done (K(i+1) may remain in flight)
        __syncthreads();          // P visible to all warps

        // O += P_rn @ V_rn : 4 indep chains, 1 MMA per pair
        #pragma unroll
        for (int kk = 0; kk < 8; kk++) {
            wmma::fragment<wmma::matrix_a, 16, 16, 8, wmma::precision::tf32, wmma::row_major> ph;
            wmma::load_matrix_sync(ph, sp + row0 * 72 + kk * 8, 72);
            #pragma unroll
            for (int j = 0; j < 4; j++) {
                wmma::fragment<wmma::matrix_b, 16, 16, 8, wmma::precision::tf32, wmma::row_major> vv_;
                wmma::load_matrix_sync(vv_, vt + (kk * 8) * 72 + j * 16, 72);
                wmma::mma_sync(oacc[j], ph, vv_, oacc[j]);
            }
        }
    }

    lpart[te * 2 + (tid & 1)] = lacc;
    __syncthreads();              // PV readers of sp done; lpart visible
    #pragma unroll
    for (int j = 0; j < 4; j++)
        wmma::store_matrix_sync(sp + row0 * 72 + j * 16, oacc[j], 72, wmma::mem_row_major);
    __syncthreads();
    for (int i = tid; i < 1024; i += 128) {
        int t = i >> 4, c4 = (i & 15) * 4;
        float inv = 1.0f / (lpart[t * 2] + lpart[t * 2 + 1]);
        float4 o = *(float4*)(sp + t * 72 + c4);
        o.x *= inv; o.y *= inv; o.z *= inv; o.w *= inv;
        float4 hi, lo; split4(o, hi, lo);
        size_t idx = (size_t)(t0 + t) * Bn * En + (size_t)b * En + h * 64 + c4;
        *(float4*)(out_hi + idx) = hi;
        *(float4*)(out_lo + idx) = lo;
    }
}

// ---------------------------------------------------------------------------
extern "C" void kernel_launch(void* const* d_in, const int* in_sizes, int n_in,
                              void* d_out, int out_size)
{
    (void)in_sizes; (void)n_in; (void)out_size;
    const float* x  = (const float*)d_in[0];
    const int* mask = (const int*)d_in[1];
    const float* bias = (const float*)d_in[2];
    const float* Wq = (const float*)d_in[3];
    const float* bq = (const float*)d_in[4];
    const float* Wk = (const float*)d_in[5];
    const float* bk = (const float*)d_in[6];
    const float* Wv = (const float*)d_in[7];
    const float* bv = (const float*)d_in[8];
    const float* Wo = (const float*)d_in[9];
    const float* bo = (const float*)d_in[10];
    float* out = (float*)d_out;

    void *pq, *pk, *pv, *pa, *pal;
    cudaGetSymbolAddress(&pq, g_q);
    cudaGetSymbolAddress(&pk, g_k);
    cudaGetSymbolAddress(&pv, g_v);
    cudaGetSymbolAddress(&pa, g_attn);
    cudaGetSymbolAddress(&pal, g_alo);

    const int GEMM_SMEM = 2 * 6912 * 4;                    // 55296 B -> 4 CTAs/SM
    const int ATTN_SMEM = (4 * 4608 + 128 + 64) * 4;       // 74496 B -> 3 CTAs/SM
    cudaFuncSetAttribute(gemm_qkv_kernel, cudaFuncAttributeMaxDynamicSharedMemorySize, GEMM_SMEM);
    cudaFuncSetAttribute(gemm_out_kernel, cudaFuncAttributeMaxDynamicSharedMemorySize, GEMM_SMEM);
    cudaFuncSetAttribute(attn_kernel, cudaFuncAttributeMaxDynamicSharedMemorySize, ATTN_SMEM);

    prep_kernel<<<1184, 256>>>(x, Wq, Wk, Wv, Wo);

    dim3 qkvgrid(En / 64, Mn / 64, 3);    // (16, 64, 3)
    gemm_qkv_kernel<<<qkvgrid, 128, GEMM_SMEM>>>(bq, bk, bv);

    dim3 agrid(Tn / 64, Bn * Hn);         // (32, 32)
    attn_kernel<<<agrid, 128, ATTN_SMEM>>>((const float*)pq, (const float*)pk,
                                           (const float*)pv, bias, mask,
                                           (float*)pa, (float*)pal);

    dim3 ggrid(En / 64, Mn / 64);         // (16, 64)
    gemm_out_kernel<<<ggrid, 128, GEMM_SMEM>>>(bo, out);
}